// round 16
// baseline (speedup 1.0000x reference)
#include <cuda_runtime.h>

#define NC 62
#define HW_BITS 18
#define HW (1 << HW_BITS)
#define NP (8 * HW)                      // 2,097,152 pixels
#define NTHREADS 128
#define NBLOCKS 8192
#define TILE_PX 32
#define NTILES (NP / TILE_PX)            // 65536
#define TILES_PER_CTA (NTILES / NBLOCKS) // 8
#define STAGES 2
#define RS 36                            // row stride: 32 px + 4 pad (conflict-free)
#define TILE_FLOATS (NC * RS)            // 2232
#define STAGE_FLOATS TILE_FLOATS
#define STAGE_BYTES (STAGE_FLOATS * 4)   // 8928
#define SMEM_BYTES (STAGES * STAGE_BYTES + 128)  // pad tail for guarded-load safety
#define IGN 255
#define SMOOTH 1e-6f
#define PAD 32
// CTA tile t -> n = t (tiles are blockIdx.x + t*8192, and 8192 tiles = 1 batch
// image), hw0 = blockIdx.x*32 CONSTANT. So src advances by a fixed stride:
#define SRC_TILE_STRIDE (62LL << (HW_BITS + 2))  // 65,011,712 B per tile step
#define SRC_K_STRIDE (1 << 24)                   // +16 channels = 16MB
#define DST_K_STRIDE (16 * RS * 4)               // 2304 B

__device__ float g_acc[NC * PAD];
__device__ float g_inter[NC * PAD];
__device__ float g_tgt[NC * PAD];
__device__ unsigned int g_count;

// 4 chunks per thread at fixed offsets from one base (k3 predicated: c=48+cc<62)
__device__ __forceinline__ void fill_tile(const char* src, unsigned dst, bool k3) {
    asm volatile("cp.async.cg.shared.global [%0], [%1], 16;"
                 :: "r"(dst), "l"(src));
    asm volatile("cp.async.cg.shared.global [%0], [%1], 16;"
                 :: "r"(dst + DST_K_STRIDE), "l"(src + SRC_K_STRIDE));
    asm volatile("cp.async.cg.shared.global [%0], [%1], 16;"
                 :: "r"(dst + 2 * DST_K_STRIDE), "l"(src + 2 * SRC_K_STRIDE));
    if (k3)
        asm volatile("cp.async.cg.shared.global [%0], [%1], 16;"
                     :: "r"(dst + 3 * DST_K_STRIDE), "l"(src + 3 * SRC_K_STRIDE));
}

__global__ __launch_bounds__(NTHREADS, 8) void dice_kernel(
    const float* __restrict__ pred, const int* __restrict__ target,
    float* __restrict__ out) {
    extern __shared__ float smem[];
    __shared__ float s_acc[NC];
    __shared__ float s_inter[NC];
    __shared__ float s_tgt[NC];
    __shared__ bool s_last;

    int tid = threadIdx.x;
    int lane = tid & 31;
    int w = tid >> 5;        // warp 0..3, pixels [w*8, w*8+8)
    int h = lane & 15;       // channel chunk: c = j*16 + h
    int q = lane >> 4;       // pixel quad 0..1
    int pxb = w * 8 + q * 4;

    if (tid < NC) {
        s_acc[tid] = 0.0f;
        s_inter[tid] = 0.0f;
        s_tgt[tid] = 0.0f;
    }

    // ---- hoisted fill state (tile-invariant except one stride) ----
    int cc = tid >> 3, ch = tid & 7;
    bool k3 = (tid < 112);   // c = 48+cc < 62
    const char* src = (const char*)(pred + (((size_t)cc) << HW_BITS) +
                                    ((size_t)blockIdx.x << 5) + (size_t)(ch * 4));
    unsigned dst0 = (unsigned)__cvta_generic_to_shared(smem) +
                    (unsigned)((cc * RS + ch * 4) * 4);

    // Prologue: fill stage0 (t=0), stage1 (t=1)
    fill_tile(src, dst0, k3);
    asm volatile("cp.async.commit_group;");
    src += SRC_TILE_STRIDE;
    fill_tile(src, dst0 + STAGE_BYTES, k3);
    asm volatile("cp.async.commit_group;");
    src += SRC_TILE_STRIDE;
    unsigned dst_cur = dst0;         // next fill (t=2) -> stage0
    int dtog = STAGE_BYTES;

    // ---- target prefetch (one tile ahead, straight from global) ----
    const int4* tcur = (const int4*)(target + ((size_t)blockIdx.x << 5)) + (pxb >> 2);
    int4 t4n = __ldg(tcur);

    float acc[4];
#pragma unroll
    for (int j = 0; j < 4; j++) acc[j] = 0.0f;

#pragma unroll 1
    for (int i = 0; i < TILES_PER_CTA; i++) {
        asm volatile("cp.async.wait_group 1;");
        __syncthreads();   // stage (i&1) resident

        int4 t4 = t4n;
        if (i + 1 < TILES_PER_CTA) {
            tcur += (1 << 16);           // +2^18 px = +2^16 int4
            t4n = __ldg(tcur);           // hidden under this tile's compute
        }

        float* st = smem + (i & 1) * STAGE_FLOATS;
        const float* p = st + h * RS + pxb;

        // Phase A: 4 LDS.128, conflict-free (bank = 4h + const)
        float4 v[4];
#pragma unroll
        for (int j = 0; j < 4; j++) {
            v[j] = (j * 16 + h < NC) ? *(const float4*)(p + j * 16 * RS)
                                     : make_float4(0.f, 0.f, 0.f, 0.f);
        }

        // Phase B: exp in place + per-pixel partial Z
        float zx = 0.f, zy = 0.f, zz = 0.f, zw = 0.f;
#pragma unroll
        for (int j = 0; j < 4; j++) {
            bool cv = (j * 16 + h < NC);
            float ex = cv ? __expf(v[j].x) : 0.f;
            float ey = cv ? __expf(v[j].y) : 0.f;
            float ez = cv ? __expf(v[j].z) : 0.f;
            float ew = cv ? __expf(v[j].w) : 0.f;
            v[j].x = ex; v[j].y = ey; v[j].z = ez; v[j].w = ew;
            zx += ex; zy += ey; zz += ez; zw += ew;
        }
        // combine Z across the 16 h-lanes (4 independent chains)
        zx += __shfl_xor_sync(0xffffffffu, zx, 1);
        zy += __shfl_xor_sync(0xffffffffu, zy, 1);
        zz += __shfl_xor_sync(0xffffffffu, zz, 1);
        zw += __shfl_xor_sync(0xffffffffu, zw, 1);
        zx += __shfl_xor_sync(0xffffffffu, zx, 2);
        zy += __shfl_xor_sync(0xffffffffu, zy, 2);
        zz += __shfl_xor_sync(0xffffffffu, zz, 2);
        zw += __shfl_xor_sync(0xffffffffu, zw, 2);
        zx += __shfl_xor_sync(0xffffffffu, zx, 4);
        zy += __shfl_xor_sync(0xffffffffu, zy, 4);
        zz += __shfl_xor_sync(0xffffffffu, zz, 4);
        zw += __shfl_xor_sync(0xffffffffu, zw, 4);
        zx += __shfl_xor_sync(0xffffffffu, zx, 8);
        zy += __shfl_xor_sync(0xffffffffu, zy, 8);
        zz += __shfl_xor_sync(0xffffffffu, zz, 8);
        zw += __shfl_xor_sync(0xffffffffu, zw, 8);

        float sx = (t4.x != IGN) ? __fdividef(1.f, zx) : 0.f;  // invZ * validf
        float sy = (t4.y != IGN) ? __fdividef(1.f, zy) : 0.f;
        float sz = (t4.z != IGN) ? __fdividef(1.f, zz) : 0.f;
        float sw = (t4.w != IGN) ? __fdividef(1.f, zw) : 0.f;

        // Phase C: per-class register accumulation
#pragma unroll
        for (int j = 0; j < 4; j++) {
            acc[j] = fmaf(v[j].x, sx,
                     fmaf(v[j].y, sy,
                     fmaf(v[j].z, sz,
                     fmaf(v[j].w, sw, acc[j]))));
        }

        // Phase D: lanes h<4 own pixel pxb+h; gather from smem, plain atomics
        if (h < 4) {
            int tmine = (h == 0) ? t4.x : (h == 1) ? t4.y : (h == 2) ? t4.z : t4.w;
            float smine = (h == 0) ? sx : (h == 1) ? sy : (h == 2) ? sz : sw;
            bool valid = (tmine != IGN);
            int tc = valid ? tmine : 0;
            float xt = st[tc * RS + pxb + h];
            atomicAdd(&s_inter[tc], __expf(xt) * smine);  // 0 if invalid
            if (valid) atomicAdd(&s_tgt[tc], 1.0f);
        }

        __syncthreads();   // stage free before refill
        if (i + 2 < TILES_PER_CTA) {
            fill_tile(src, dst_cur, k3);
            src += SRC_TILE_STRIDE;
            dst_cur += dtog;
            dtog = -dtog;
        }
        asm volatile("cp.async.commit_group;");  // uniform group count
    }

    // Reduce acc across the 2 q-groups (xor 16), then to shared
#pragma unroll
    for (int j = 0; j < 4; j++) {
        float va = acc[j];
        va += __shfl_xor_sync(0xffffffffu, va, 16);
        if (lane < 16) {
            int c = j * 16 + lane;
            if (c < NC) atomicAdd(&s_acc[c], va);
        }
    }
    __syncthreads();

    // One global atomic per class per block (padded -> spread L2 slices)
    if (tid < NC) {
        atomicAdd(&g_acc[tid * PAD], s_acc[tid]);
        atomicAdd(&g_inter[tid * PAD], s_inter[tid]);
        atomicAdd(&g_tgt[tid * PAD], s_tgt[tid]);
    }
    __threadfence();
    __syncthreads();
    if (tid == 0) {
        unsigned prev = atomicAdd(&g_count, 1u);
        s_last = (prev == NBLOCKS - 1);
    }
    __syncthreads();
    if (!s_last) return;

    // ---- last block: finalize ----
    float dice = 0.0f, has = 0.0f;
    if (tid < NC) {
        float ps = atomicAdd(&g_acc[tid * PAD], 0.0f);
        float iv = atomicAdd(&g_inter[tid * PAD], 0.0f);
        float tg = atomicAdd(&g_tgt[tid * PAD], 0.0f);
        float un = ps + tg;
        if (un > 0.0f) {
            has = 1.0f;
            dice = (2.0f * iv + SMOOTH) / (un + SMOOTH);
        }
    }
    __shared__ float sd[4], sh[4];
#pragma unroll
    for (int o = 16; o > 0; o >>= 1) {
        dice += __shfl_xor_sync(0xffffffffu, dice, o);
        has += __shfl_xor_sync(0xffffffffu, has, o);
    }
    if (lane == 0) {
        sd[tid >> 5] = dice;
        sh[tid >> 5] = has;
    }
    __syncthreads();
    if (tid == 0) {
        float ds = 0.0f, hs = 0.0f;
#pragma unroll
        for (int ww = 0; ww < NTHREADS / 32; ww++) {
            ds += sd[ww];
            hs += sh[ww];
        }
        float mean = (hs > 0.0f) ? (ds / fmaxf(hs, 1.0f)) : 1.0f;
        out[0] = 1.0f - mean;
    }
    __syncthreads();
    // reset globals so every graph replay starts clean
    if (tid < NC) {
        g_acc[tid * PAD] = 0.0f;
        g_inter[tid * PAD] = 0.0f;
        g_tgt[tid * PAD] = 0.0f;
    }
    if (tid == 0) g_count = 0;
}

extern "C" void kernel_launch(void* const* d_in, const int* in_sizes, int n_in,
                              void* d_out, int out_size) {
    const float* pred = (const float*)d_in[0];
    const int* target = (const int*)d_in[1];
    float* out = (float*)d_out;
    cudaFuncSetAttribute(dice_kernel, cudaFuncAttributeMaxDynamicSharedMemorySize,
                         SMEM_BYTES);
    dice_kernel<<<NBLOCKS, NTHREADS, SMEM_BYTES>>>(pred, target, out);
}